// round 1
// baseline (speedup 1.0000x reference)
#include <cuda_runtime.h>

#define BB    16
#define NTOK  1024            // H*W = 32*32
#define CC    512
#define M_TOT (BB * NTOK)     // 16384
#define NH    8
#define DH    64
#define QKV_N (NH * DH * 3)   // 1536
#define ATT_N (NH * DH)       // 512
#define SCALE 0.125f          // 1/sqrt(64)

// Scratch (static device globals: allocation-free kernel_launch)
__device__ float g_qkv[(size_t)M_TOT * QKV_N];   // ~100 MB
__device__ float g_att[(size_t)M_TOT * ATT_N];   // ~32 MB

// ---------------------------------------------------------------------------
// Tiled fp32 GEMM: C[M,N] = A[M,K] @ B[K,N] + bias[N] (+ residual[M,N])
// BM=BN=128, BK=16, 256 threads, 8x8 per-thread register tile.
// M % 128 == 0, N % 128 == 0, K % 16 == 0 assumed (true for all calls here).
// ---------------------------------------------------------------------------
template <bool RES>
__global__ __launch_bounds__(256) void sgemm128(
    const float* __restrict__ A, const float* __restrict__ Bm,
    const float* __restrict__ bias, const float* __restrict__ resid,
    float* __restrict__ C, int M, int N, int K)
{
    __shared__ float As[16][128];   // transposed: As[k][m]
    __shared__ float Bs[16][128];   // Bs[k][n]

    const int bx = blockIdx.x;          // N tile
    const int by = blockIdx.y;          // M tile
    const int tid = threadIdx.x;
    const int tx = tid & 15;            // N direction (8 cols each)
    const int ty = tid >> 4;            // M direction (8 rows each)

    // A loader: 128 rows x 16 cols = 512 float4; 256 thr -> 2 each
    const int a_row = tid >> 2;         // 0..63
    const int a_c4  = tid & 3;          // 0..3  (float4 column group)
    // B loader: 16 rows x 128 cols = 512 float4; 256 thr -> 2 each
    const int b_row = tid >> 5;         // 0..7
    const int b_c4  = tid & 31;         // 0..31

    float acc[8][8];
#pragma unroll
    for (int i = 0; i < 8; i++)
#pragma unroll
        for (int j = 0; j < 8; j++) acc[i][j] = 0.f;

    for (int k0 = 0; k0 < K; k0 += 16) {
        // load A tile (transpose into As)
#pragma unroll
        for (int p = 0; p < 2; p++) {
            int r = a_row + p * 64;
            float4 v = *(const float4*)(A + (size_t)(by * 128 + r) * K + k0 + a_c4 * 4);
            As[a_c4 * 4 + 0][r] = v.x;
            As[a_c4 * 4 + 1][r] = v.y;
            As[a_c4 * 4 + 2][r] = v.z;
            As[a_c4 * 4 + 3][r] = v.w;
        }
        // load B tile
#pragma unroll
        for (int p = 0; p < 2; p++) {
            int r = b_row + p * 8;
            *(float4*)&Bs[r][b_c4 * 4] =
                *(const float4*)(Bm + (size_t)(k0 + r) * N + bx * 128 + b_c4 * 4);
        }
        __syncthreads();

#pragma unroll
        for (int k = 0; k < 16; k++) {
            float4 a0 = *(const float4*)&As[k][ty * 8];
            float4 a1 = *(const float4*)&As[k][ty * 8 + 4];
            float4 b0 = *(const float4*)&Bs[k][tx * 8];
            float4 b1 = *(const float4*)&Bs[k][tx * 8 + 4];
            float ra[8] = {a0.x, a0.y, a0.z, a0.w, a1.x, a1.y, a1.z, a1.w};
            float rb[8] = {b0.x, b0.y, b0.z, b0.w, b1.x, b1.y, b1.z, b1.w};
#pragma unroll
            for (int i = 0; i < 8; i++)
#pragma unroll
                for (int j = 0; j < 8; j++) acc[i][j] += ra[i] * rb[j];
        }
        __syncthreads();
    }

    // epilogue: + bias (+ residual), float4 stores
#pragma unroll
    for (int i = 0; i < 8; i++) {
        int row = by * 128 + ty * 8 + i;
#pragma unroll
        for (int j4 = 0; j4 < 2; j4++) {
            int col = bx * 128 + tx * 8 + j4 * 4;
            float4 bz = *(const float4*)(bias + col);
            float4 r;
            r.x = acc[i][j4 * 4 + 0] + bz.x;
            r.y = acc[i][j4 * 4 + 1] + bz.y;
            r.z = acc[i][j4 * 4 + 2] + bz.z;
            r.w = acc[i][j4 * 4 + 3] + bz.w;
            if (RES) {
                float4 rr = *(const float4*)(resid + (size_t)row * N + col);
                r.x += rr.x; r.y += rr.y; r.z += rr.z; r.w += rr.w;
            }
            *(float4*)(C + (size_t)row * N + col) = r;
        }
    }
}

// ---------------------------------------------------------------------------
// Flash-style attention. Grid: (qblocks=8, heads=8, batch=16), 128 threads.
// Each thread owns one query row: q[64] and O[64] in registers; K/V tiles
// of 32 keys in shared memory; online softmax (m, l) per thread.
// qkv layout: [b*1024 + x][h*192 + {q:0, k:64, v:128} + d]
// ---------------------------------------------------------------------------
__global__ __launch_bounds__(128) void attn_kernel(
    const float* __restrict__ qkv, float* __restrict__ out)
{
    const int t = threadIdx.x;
    const int qb = blockIdx.x;
    const int h  = blockIdx.y;
    const int b  = blockIdx.z;
    const int x  = qb * 128 + t;

    __shared__ float Ks[32][64];
    __shared__ float Vs[32][64];

    const float* qp = qkv + ((size_t)(b * NTOK + x)) * QKV_N + h * 192;
    float q[64];
#pragma unroll
    for (int d = 0; d < 64; d += 4) {
        float4 v = *(const float4*)(qp + d);
        q[d + 0] = v.x * SCALE; q[d + 1] = v.y * SCALE;
        q[d + 2] = v.z * SCALE; q[d + 3] = v.w * SCALE;
    }

    float O[64];
#pragma unroll
    for (int d = 0; d < 64; d++) O[d] = 0.f;
    float m = -1e30f, l = 0.f;

    const float* kvbase = qkv + (size_t)b * NTOK * QKV_N + h * 192;

    for (int kt = 0; kt < NTOK; kt += 32) {
        // cooperative load: 32 rows x 16 float4 per tile, 128 thr -> 4 each
#pragma unroll
        for (int r = 0; r < 4; r++) {
            int idx = t + r * 128;       // 0..511
            int row = idx >> 4;
            int c4  = idx & 15;
            const float* src = kvbase + (size_t)(kt + row) * QKV_N + 64 + c4 * 4;
            *(float4*)&Ks[row][c4 * 4] = *(const float4*)src;         // K
            *(float4*)&Vs[row][c4 * 4] = *(const float4*)(src + 64);  // V
        }
        __syncthreads();

        // scores vs 32 keys (4-wide partial sums for ILP)
        float s[32];
#pragma unroll
        for (int j = 0; j < 32; j++) {
            float ax = 0.f, ay = 0.f, az = 0.f, aw = 0.f;
#pragma unroll
            for (int d = 0; d < 64; d += 4) {
                float4 kv = *(const float4*)&Ks[j][d];
                ax += q[d + 0] * kv.x;
                ay += q[d + 1] * kv.y;
                az += q[d + 2] * kv.z;
                aw += q[d + 3] * kv.w;
            }
            s[j] = (ax + ay) + (az + aw);
        }

        // online softmax update
        float mt = m;
#pragma unroll
        for (int j = 0; j < 32; j++) mt = fmaxf(mt, s[j]);
        float alpha = __expf(m - mt);
        float ls = 0.f;
#pragma unroll
        for (int j = 0; j < 32; j++) { s[j] = __expf(s[j] - mt); ls += s[j]; }
        l = l * alpha + ls;
        m = mt;
#pragma unroll
        for (int d = 0; d < 64; d++) O[d] *= alpha;

        // O += P @ V
#pragma unroll
        for (int j = 0; j < 32; j++) {
            float p = s[j];
#pragma unroll
            for (int d = 0; d < 64; d += 4) {
                float4 vv = *(const float4*)&Vs[j][d];
                O[d + 0] += p * vv.x;
                O[d + 1] += p * vv.y;
                O[d + 2] += p * vv.z;
                O[d + 3] += p * vv.w;
            }
        }
        __syncthreads();
    }

    float inv = 1.f / l;
    float* op = out + ((size_t)(b * NTOK + x)) * ATT_N + h * 64;
#pragma unroll
    for (int d = 0; d < 64; d += 4) {
        float4 v;
        v.x = O[d + 0] * inv; v.y = O[d + 1] * inv;
        v.z = O[d + 2] * inv; v.w = O[d + 3] * inv;
        *(float4*)(op + d) = v;
    }
}

// ---------------------------------------------------------------------------
extern "C" void kernel_launch(void* const* d_in, const int* in_sizes, int n_in,
                              void* d_out, int out_size)
{
    const float* ft    = (const float*)d_in[0];  // [16,32,32,512] == X[16384,512]
    const float* w_qkv = (const float*)d_in[1];  // [512,1536]
    const float* b_qkv = (const float*)d_in[2];  // [1536]
    const float* w_out = (const float*)d_in[3];  // [512,512]
    const float* b_out = (const float*)d_in[4];  // [512]
    float* out = (float*)d_out;

    float* qkv; float* att;
    cudaGetSymbolAddress((void**)&qkv, g_qkv);
    cudaGetSymbolAddress((void**)&att, g_att);

    // 1) QKV projection: [16384,1536] = X @ w_qkv + b_qkv
    {
        dim3 grid(QKV_N / 128, M_TOT / 128);
        sgemm128<false><<<grid, 256>>>(ft, w_qkv, b_qkv, nullptr, qkv,
                                       M_TOT, QKV_N, CC);
    }
    // 2) attention per (qblock, head, batch)
    {
        dim3 grid(NTOK / 128, NH, BB);
        attn_kernel<<<grid, 128>>>(qkv, att);
    }
    // 3) output projection + bias + residual
    {
        dim3 grid(ATT_N / 128, M_TOT / 128);
        sgemm128<true><<<grid, 256>>>(att, w_out, b_out, ft, out,
                                      M_TOT, ATT_N, CC);
    }
}

// round 2
// speedup vs baseline: 3.3224x; 3.3224x over previous
#include <cuda_runtime.h>
#include <cstdint>

#define BB    16
#define NTOK  1024
#define CC    512
#define M_TOT (BB * NTOK)     // 16384
#define NH    8
#define DH    64
#define QKV_N 1536
#define ATT_N 512
#define SCALE 0.125f

__device__ float g_qkv[(size_t)M_TOT * QKV_N];
__device__ float g_att[(size_t)M_TOT * ATT_N];

__device__ __forceinline__ float f2tf(float x) {
    uint32_t r;
    asm("cvt.rna.tf32.f32 %0, %1;" : "=r"(r) : "f"(x));
    return __uint_as_float(r);
}

__device__ __forceinline__ void mma_tf32(float* d, const uint32_t* a, const uint32_t* b) {
    asm volatile(
        "mma.sync.aligned.m16n8k8.row.col.f32.tf32.tf32.f32 "
        "{%0,%1,%2,%3}, {%4,%5,%6,%7}, {%8,%9}, {%0,%1,%2,%3};"
        : "+f"(d[0]), "+f"(d[1]), "+f"(d[2]), "+f"(d[3])
        : "r"(a[0]), "r"(a[1]), "r"(a[2]), "r"(a[3]), "r"(b[0]), "r"(b[1]));
}

// ---------------------------------------------------------------------------
// tf32 tensor-core GEMM: C = A[M,K] @ B[K,N] + bias (+resid)
// BM=128, BN=128, BK=16, 256 threads (8 warps, 4x2), warp tile 32x64.
// ---------------------------------------------------------------------------
template <bool RES>
__global__ __launch_bounds__(256) void tgemm(
    const float* __restrict__ A, const float* __restrict__ B,
    const float* __restrict__ bias, const float* __restrict__ resid,
    float* __restrict__ C, int M, int N, int K)
{
    __shared__ __align__(16) float As[2][128][20];   // [m][k], pad 4
    __shared__ __align__(16) float Bs[2][16][136];   // [k][n], pad 8

    const int tid  = threadIdx.x;
    const int warp = tid >> 5, lane = tid & 31;
    const int gid  = lane >> 2, tig = lane & 3;
    const int wr   = warp >> 1, wc = warp & 1;
    const int bx = blockIdx.x, by = blockIdx.y;

    const int am  = tid >> 2;    // 0..63
    const int ac4 = tid & 3;     // 0..3
    const int bk  = tid >> 4;    // 0..15
    const int bc4 = tid & 15;    // 0..15

    const float* Ag = A + (size_t)(by * 128) * K;
    const float* Bg = B + (size_t)bx * 128;

    float acc[2][8][4];
#pragma unroll
    for (int mt = 0; mt < 2; mt++)
#pragma unroll
        for (int nt = 0; nt < 8; nt++)
#pragma unroll
            for (int r = 0; r < 4; r++) acc[mt][nt][r] = 0.f;

    float4 ra[2], rb[2];

    auto ldg = [&](int k0) {
#pragma unroll
        for (int p = 0; p < 2; p++)
            ra[p] = *(const float4*)(Ag + (size_t)(am + p * 64) * K + k0 + ac4 * 4);
#pragma unroll
        for (int p = 0; p < 2; p++)
            rb[p] = *(const float4*)(Bg + (size_t)(k0 + bk) * N + bc4 * 4 + p * 64);
    };
    auto sts = [&](int buf) {
#pragma unroll
        for (int p = 0; p < 2; p++) {
            float4 v = ra[p];
            v.x = f2tf(v.x); v.y = f2tf(v.y); v.z = f2tf(v.z); v.w = f2tf(v.w);
            *(float4*)&As[buf][am + p * 64][ac4 * 4] = v;
        }
#pragma unroll
        for (int p = 0; p < 2; p++) {
            float4 v = rb[p];
            v.x = f2tf(v.x); v.y = f2tf(v.y); v.z = f2tf(v.z); v.w = f2tf(v.w);
            *(float4*)&Bs[buf][bk][bc4 * 4 + p * 64] = v;
        }
    };

    const int tiles = K >> 4;
    ldg(0);
    sts(0);
    __syncthreads();
    int buf = 0;

    for (int t = 0; t < tiles; t++) {
        if (t + 1 < tiles) ldg((t + 1) << 4);

#pragma unroll
        for (int kk = 0; kk < 16; kk += 8) {
            uint32_t af[2][4], bf[8][2];
#pragma unroll
            for (int mt = 0; mt < 2; mt++) {
                int mb = wr * 32 + mt * 16;
                af[mt][0] = __float_as_uint(As[buf][mb + gid    ][kk + tig]);
                af[mt][1] = __float_as_uint(As[buf][mb + gid + 8][kk + tig]);
                af[mt][2] = __float_as_uint(As[buf][mb + gid    ][kk + tig + 4]);
                af[mt][3] = __float_as_uint(As[buf][mb + gid + 8][kk + tig + 4]);
            }
#pragma unroll
            for (int nt = 0; nt < 8; nt++) {
                int nb = wc * 64 + nt * 8;
                bf[nt][0] = __float_as_uint(Bs[buf][kk + tig    ][nb + gid]);
                bf[nt][1] = __float_as_uint(Bs[buf][kk + tig + 4][nb + gid]);
            }
#pragma unroll
            for (int mt = 0; mt < 2; mt++)
#pragma unroll
                for (int nt = 0; nt < 8; nt++)
                    mma_tf32(acc[mt][nt], af[mt], bf[nt]);
        }

        if (t + 1 < tiles) sts(buf ^ 1);
        __syncthreads();
        buf ^= 1;
    }

#pragma unroll
    for (int mt = 0; mt < 2; mt++) {
#pragma unroll
        for (int r2 = 0; r2 < 2; r2++) {
            int row = by * 128 + wr * 32 + mt * 16 + gid + r2 * 8;
#pragma unroll
            for (int nt = 0; nt < 8; nt++) {
                int col = bx * 128 + wc * 64 + nt * 8 + tig * 2;
                float2 bz = *(const float2*)(bias + col);
                float2 o;
                o.x = acc[mt][nt][r2 * 2 + 0] + bz.x;
                o.y = acc[mt][nt][r2 * 2 + 1] + bz.y;
                if (RES) {
                    float2 rr = *(const float2*)(resid + (size_t)row * N + col);
                    o.x += rr.x; o.y += rr.y;
                }
                *(float2*)(C + (size_t)row * N + col) = o;
            }
        }
    }
}

// ---------------------------------------------------------------------------
// Flash attention, tensor cores. CTA = 64 queries x one (b,h); 4 warps x 16 rows.
// Swizzled smem tiles, exactly 48KB static.
// ---------------------------------------------------------------------------
#define SWA(r, c) ((r) * 64 + ((c) ^ ((((r) & 15)) << 2)))
#define SWV(r, c) ((r) * 64 + ((c) ^ ((((r) & 3)) << 3)))

__global__ __launch_bounds__(128) void fattn(
    const float* __restrict__ qkv, float* __restrict__ out)
{
    __shared__ __align__(16) float Ks[64 * 64];
    __shared__ __align__(16) float Vs[64 * 64];
    __shared__ __align__(16) float Ps[64 * 64];

    const int tid  = threadIdx.x;
    const int warp = tid >> 5, lane = tid & 31;
    const int gid  = lane >> 2, tig = lane & 3;
    const int wrow = warp * 16;
    const int qt = blockIdx.x, h = blockIdx.y, b = blockIdx.z;

    const float* base = qkv + ((size_t)b * NTOK) * QKV_N + h * 192;

    // ---- load Q tile (scaled, tf32) into Ks, extract frags ----
#pragma unroll
    for (int i = 0; i < 8; i++) {
        int idx = tid + i * 128;
        int r = idx >> 4, c4 = idx & 15;
        float4 v = *(const float4*)(base + (size_t)(qt * 64 + r) * QKV_N + c4 * 4);
        v.x = f2tf(v.x * SCALE); v.y = f2tf(v.y * SCALE);
        v.z = f2tf(v.z * SCALE); v.w = f2tf(v.w * SCALE);
        *(float4*)&Ks[SWA(r, c4 * 4)] = v;
    }
    __syncthreads();

    uint32_t qf[8][4];
#pragma unroll
    for (int kk = 0; kk < 8; kk++) {
        qf[kk][0] = __float_as_uint(Ks[SWA(wrow + gid,     kk * 8 + tig)]);
        qf[kk][1] = __float_as_uint(Ks[SWA(wrow + gid + 8, kk * 8 + tig)]);
        qf[kk][2] = __float_as_uint(Ks[SWA(wrow + gid,     kk * 8 + tig + 4)]);
        qf[kk][3] = __float_as_uint(Ks[SWA(wrow + gid + 8, kk * 8 + tig + 4)]);
    }
    __syncthreads();

    float o[8][4];
#pragma unroll
    for (int nt = 0; nt < 8; nt++)
#pragma unroll
        for (int r = 0; r < 4; r++) o[nt][r] = 0.f;
    float m0 = -1e30f, m1 = -1e30f, l0 = 0.f, l1 = 0.f;

    for (int kt = 0; kt < 16; kt++) {
        const float* kb = base + (size_t)(kt * 64) * QKV_N;
#pragma unroll
        for (int i = 0; i < 8; i++) {
            int idx = tid + i * 128;
            int r = idx >> 4, c4 = idx & 15;
            const float* src = kb + (size_t)r * QKV_N + 64 + c4 * 4;
            float4 v = *(const float4*)src;
            v.x = f2tf(v.x); v.y = f2tf(v.y); v.z = f2tf(v.z); v.w = f2tf(v.w);
            *(float4*)&Ks[SWA(r, c4 * 4)] = v;
            float4 w = *(const float4*)(src + 64);
            w.x = f2tf(w.x); w.y = f2tf(w.y); w.z = f2tf(w.z); w.w = f2tf(w.w);
            *(float4*)&Vs[SWV(r, c4 * 4)] = w;
        }
        __syncthreads();

        // S = Q @ K^T
        float s[8][4];
#pragma unroll
        for (int nt = 0; nt < 8; nt++)
#pragma unroll
            for (int r = 0; r < 4; r++) s[nt][r] = 0.f;
#pragma unroll
        for (int kk = 0; kk < 8; kk++) {
#pragma unroll
            for (int nt = 0; nt < 8; nt++) {
                uint32_t bfr[2];
                bfr[0] = __float_as_uint(Ks[SWA(nt * 8 + gid, kk * 8 + tig)]);
                bfr[1] = __float_as_uint(Ks[SWA(nt * 8 + gid, kk * 8 + tig + 4)]);
                mma_tf32(s[nt], qf[kk], bfr);
            }
        }

        // online softmax
        float mx0 = -1e30f, mx1 = -1e30f;
#pragma unroll
        for (int nt = 0; nt < 8; nt++) {
            mx0 = fmaxf(mx0, fmaxf(s[nt][0], s[nt][1]));
            mx1 = fmaxf(mx1, fmaxf(s[nt][2], s[nt][3]));
        }
        mx0 = fmaxf(mx0, __shfl_xor_sync(0xffffffffu, mx0, 1));
        mx0 = fmaxf(mx0, __shfl_xor_sync(0xffffffffu, mx0, 2));
        mx1 = fmaxf(mx1, __shfl_xor_sync(0xffffffffu, mx1, 1));
        mx1 = fmaxf(mx1, __shfl_xor_sync(0xffffffffu, mx1, 2));

        float mn0 = fmaxf(m0, mx0), mn1 = fmaxf(m1, mx1);
        float a0 = __expf(m0 - mn0), a1 = __expf(m1 - mn1);
        m0 = mn0; m1 = mn1;
        l0 *= a0; l1 *= a1;

#pragma unroll
        for (int nt = 0; nt < 8; nt++) {
            float p0 = __expf(s[nt][0] - mn0);
            float p1 = __expf(s[nt][1] - mn0);
            float p2 = __expf(s[nt][2] - mn1);
            float p3 = __expf(s[nt][3] - mn1);
            l0 += p0 + p1; l1 += p2 + p3;
            o[nt][0] *= a0; o[nt][1] *= a0; o[nt][2] *= a1; o[nt][3] *= a1;
            float2 t0; t0.x = f2tf(p0); t0.y = f2tf(p1);
            *(float2*)&Ps[SWA(wrow + gid, nt * 8 + tig * 2)] = t0;
            float2 t1; t1.x = f2tf(p2); t1.y = f2tf(p3);
            *(float2*)&Ps[SWA(wrow + gid + 8, nt * 8 + tig * 2)] = t1;
        }
        __syncwarp();

        // O += P @ V
#pragma unroll
        for (int kk = 0; kk < 8; kk++) {
            uint32_t pa[4];
            pa[0] = __float_as_uint(Ps[SWA(wrow + gid,     kk * 8 + tig)]);
            pa[1] = __float_as_uint(Ps[SWA(wrow + gid + 8, kk * 8 + tig)]);
            pa[2] = __float_as_uint(Ps[SWA(wrow + gid,     kk * 8 + tig + 4)]);
            pa[3] = __float_as_uint(Ps[SWA(wrow + gid + 8, kk * 8 + tig + 4)]);
#pragma unroll
            for (int nt = 0; nt < 8; nt++) {
                uint32_t vb[2];
                vb[0] = __float_as_uint(Vs[SWV(kk * 8 + tig,     nt * 8 + gid)]);
                vb[1] = __float_as_uint(Vs[SWV(kk * 8 + tig + 4, nt * 8 + gid)]);
                mma_tf32(o[nt], pa, vb);
            }
        }
        __syncthreads();
    }

    // epilogue
    l0 += __shfl_xor_sync(0xffffffffu, l0, 1);
    l0 += __shfl_xor_sync(0xffffffffu, l0, 2);
    l1 += __shfl_xor_sync(0xffffffffu, l1, 1);
    l1 += __shfl_xor_sync(0xffffffffu, l1, 2);
    float i0 = 1.f / l0, i1 = 1.f / l1;

    int row = b * NTOK + qt * 64 + wrow + gid;
    float* op0 = out + (size_t)row * ATT_N + h * 64;
    float* op1 = out + (size_t)(row + 8) * ATT_N + h * 64;
#pragma unroll
    for (int nt = 0; nt < 8; nt++) {
        float2 v0; v0.x = o[nt][0] * i0; v0.y = o[nt][1] * i0;
        *(float2*)(op0 + nt * 8 + tig * 2) = v0;
        float2 v1; v1.x = o[nt][2] * i1; v1.y = o[nt][3] * i1;
        *(float2*)(op1 + nt * 8 + tig * 2) = v1;
    }
}

// ---------------------------------------------------------------------------
extern "C" void kernel_launch(void* const* d_in, const int* in_sizes, int n_in,
                              void* d_out, int out_size)
{
    const float* ft    = (const float*)d_in[0];
    const float* w_qkv = (const float*)d_in[1];
    const float* b_qkv = (const float*)d_in[2];
    const float* w_out = (const float*)d_in[3];
    const float* b_out = (const float*)d_in[4];
    float* out = (float*)d_out;

    float* qkv; float* att;
    cudaGetSymbolAddress((void**)&qkv, g_qkv);
    cudaGetSymbolAddress((void**)&att, g_att);

    {
        dim3 grid(QKV_N / 128, M_TOT / 128);
        tgemm<false><<<grid, 256>>>(ft, w_qkv, b_qkv, nullptr, qkv,
                                    M_TOT, QKV_N, CC);
    }
    {
        dim3 grid(NTOK / 64, NH, BB);
        fattn<<<grid, 128>>>(qkv, att);
    }
    {
        dim3 grid(ATT_N / 128, M_TOT / 128);
        tgemm<true><<<grid, 256>>>(att, w_out, b_out, ft, out,
                                   M_TOT, ATT_N, CC);
    }
}